// round 15
// baseline (speedup 1.0000x reference)
#include <cuda_runtime.h>
#include <cuda_fp16.h>

#define D        128
#define KNEI     32
#define MAXROWS  50176   // >= M = 50000

// Scratch (no cudaMalloc allowed):
__device__ float   g_hn[MAXROWS];           // hn[m] = h[m] . att[D..2D)  (exact f32)
__device__ __half2 g_h16[MAXROWS * (D/2)];  // fp16 copy of h (12.8 MB) for the gather

// ---------------------------------------------------------------------------
// Pass 1: single read of h (25.6 MB): compute hn[m] AND write the fp16 copy.
// ---------------------------------------------------------------------------
__global__ __launch_bounds__(256)
void prep_h(const float* __restrict__ h,
            const float* __restrict__ att,
            int M)
{
    const int gw   = (blockIdx.x * blockDim.x + threadIdx.x) >> 5;
    const int lane = threadIdx.x & 31;
    if (gw >= M) return;

    const float4 a = reinterpret_cast<const float4*>(att)[32 + lane];
    const float4 v = reinterpret_cast<const float4*>(h + (size_t)gw * D)[lane];

    __half2 p0 = __floats2half2_rn(v.x, v.y);
    __half2 p1 = __floats2half2_rn(v.z, v.w);
    uint2 packed;
    packed.x = *reinterpret_cast<unsigned int*>(&p0);
    packed.y = *reinterpret_cast<unsigned int*>(&p1);
    reinterpret_cast<uint2*>(g_h16 + (size_t)gw * (D/2))[lane] = packed;

    float p = fmaf(v.x, a.x, fmaf(v.y, a.y, fmaf(v.z, a.z, v.w * a.w)));
    #pragma unroll
    for (int o = 16; o; o >>= 1)
        p += __shfl_xor_sync(0xffffffffu, p, o);
    if (lane == 0) g_hn[gw] = p;
}

// ---------------------------------------------------------------------------
// Pass 2: one warp per output row. f32-exact scores -> warp softmax (weights
// stored in SMEM as replicated half2) -> fp16 weighted gather with depth-2
// pipeline; INNER REDUCTION IN HALF2: 4 neighbors are combined with
// HMUL2+3xHFMA2 per dim-pair, then ONE convert to f32 per partial.
// Cuts hot-loop math slots ~43% vs per-neighbor f32 converts.
// ---------------------------------------------------------------------------
__global__ __launch_bounds__(256, 5)
void gat_main(const int*   __restrict__ nei,
              const float* __restrict__ h_refer,
              const float* __restrict__ att,
              float*       __restrict__ out,
              int N)
{
    __shared__ int      s_idx[8][KNEI];
    __shared__ unsigned s_wh[8][KNEI];   // half2(w,w) bit patterns

    const int warp = threadIdx.x >> 5;
    const int lane = threadIdx.x & 31;
    const int n    = blockIdx.x * 8 + warp;
    if (n >= N) return;

    // ---- score phase (f32-exact) -------------------------------------------
    const float4 aref = reinterpret_cast<const float4*>(att)[lane];
    const float4 hr   = __ldcs(&reinterpret_cast<const float4*>(
                                    h_refer + (size_t)n * D)[lane]);
    float sref = fmaf(hr.x, aref.x, fmaf(hr.y, aref.y,
                 fmaf(hr.z, aref.z, hr.w * aref.w)));
    #pragma unroll
    for (int o = 16; o; o >>= 1)
        sref += __shfl_xor_sync(0xffffffffu, sref, o);

    const int idx = __ldcs(&nei[(size_t)n * KNEI + lane]);   // 128B coalesced
    float s = sref + g_hn[idx];
    s = fmaxf(s, 0.01f * s);                                 // leaky_relu(0.01)

    float m = s;
    #pragma unroll
    for (int o = 16; o; o >>= 1)
        m = fmaxf(m, __shfl_xor_sync(0xffffffffu, m, o));
    const float e = __expf(s - m);
    float sum = e;
    #pragma unroll
    for (int o = 16; o; o >>= 1)
        sum += __shfl_xor_sync(0xffffffffu, sum, o);

    const __half2 wh2 = __half2half2(__float2half_rn(e / sum));
    s_wh[warp][lane]  = *reinterpret_cast<const unsigned*>(&wh2);
    s_idx[warp][lane] = idx;
    __syncwarp();

    // ---- weighted gather: fp16 rows, depth-2 pipeline, half2 inner sums ----
    float4 acc = make_float4(0.f, 0.f, 0.f, 0.f);
    uint2 bufA[8], bufB[8];

    #pragma unroll
    for (int j = 0; j < 8; ++j)
        bufA[j] = reinterpret_cast<const uint2*>(
                      g_h16 + (size_t)s_idx[warp][j] * (D/2))[lane];
    #pragma unroll
    for (int j = 0; j < 8; ++j)
        bufB[j] = reinterpret_cast<const uint2*>(
                      g_h16 + (size_t)s_idx[warp][8 + j] * (D/2))[lane];

    #pragma unroll
    for (int g = 0; g < 4; ++g) {
        // two 4-neighbor half2 partials per 8-group
        #pragma unroll
        for (int half = 0; half < 2; ++half) {
            const uint4 wq = *reinterpret_cast<const uint4*>(
                                 &s_wh[warp][g * 8 + half * 4]);
            const __half2 w0 = *reinterpret_cast<const __half2*>(&wq.x);
            const __half2 w1 = *reinterpret_cast<const __half2*>(&wq.y);
            const __half2 w2 = *reinterpret_cast<const __half2*>(&wq.z);
            const __half2 w3 = *reinterpret_cast<const __half2*>(&wq.w);
            const uint2* b = &bufA[half * 4];

            __half2 p01 = __hmul2(*reinterpret_cast<const __half2*>(&b[0].x), w0);
            p01 = __hfma2(*reinterpret_cast<const __half2*>(&b[1].x), w1, p01);
            p01 = __hfma2(*reinterpret_cast<const __half2*>(&b[2].x), w2, p01);
            p01 = __hfma2(*reinterpret_cast<const __half2*>(&b[3].x), w3, p01);

            __half2 p23 = __hmul2(*reinterpret_cast<const __half2*>(&b[0].y), w0);
            p23 = __hfma2(*reinterpret_cast<const __half2*>(&b[1].y), w1, p23);
            p23 = __hfma2(*reinterpret_cast<const __half2*>(&b[2].y), w2, p23);
            p23 = __hfma2(*reinterpret_cast<const __half2*>(&b[3].y), w3, p23);

            const float2 f0 = __half22float2(p01);   // one convert per partial
            const float2 f1 = __half22float2(p23);
            acc.x += f0.x;  acc.y += f0.y;
            acc.z += f1.x;  acc.w += f1.y;
        }
        // rotate: A <- B (in flight), B <- group g+2
        #pragma unroll
        for (int j = 0; j < 8; ++j) bufA[j] = bufB[j];
        if (g + 2 < 4) {
            const int base = (g + 2) * 8;
            #pragma unroll
            for (int j = 0; j < 8; ++j)
                bufB[j] = reinterpret_cast<const uint2*>(
                              g_h16 + (size_t)s_idx[warp][base + j] * (D/2))[lane];
        }
    }

    // Streaming store: output is never re-read.
    __stcs(&reinterpret_cast<float4*>(out + (size_t)n * D)[lane], acc);
}

extern "C" void kernel_launch(void* const* d_in, const int* in_sizes, int n_in,
                              void* d_out, int out_size)
{
    const int*   nei     = (const int*)d_in[0];    // int32 [N, 32]
    const float* h       = (const float*)d_in[1];  // f32   [M, 128]
    const float* h_refer = (const float*)d_in[2];  // f32   [N, 128]
    const float* att     = (const float*)d_in[3];  // f32   [1, 256]
    float*       out     = (float*)d_out;          // f32   [N, 128]

    const int N = in_sizes[0] / KNEI;
    const int M = in_sizes[1] / D;

    prep_h<<<(M + 7) / 8, 256>>>(h, att, M);
    gat_main<<<(N + 7) / 8, 256>>>(nei, h_refer, att, out, N);
}